// round 2
// baseline (speedup 1.0000x reference)
#include <cuda_runtime.h>
#include <math.h>

#define NN 20000
#define EE 640000
#define GGR 64
#define HH 128
#define EIN 32

// ---------------- scratch (static device globals; no allocation) ----------------
__device__ float g_hA[NN*HH];
__device__ float g_hB[NN*HH];
__device__ float g_D1[NN*HH];
__device__ float g_D2[NN*HH];
__device__ float g_S[NN*EIN];
__device__ int   g_deg[NN];
__device__ int   g_rowptr[NN+1];
__device__ int   g_fill[NN+1];
__device__ int   g_csr_src[EE];
__device__ int   g_csr_eid[EE];
__device__ float g_M1[HH*HH], g_M2[HH*HH];
__device__ float g_T1[EIN*HH], g_T2[EIN*HH];
__device__ float g_Gm1[EIN*HH], g_Gm2[EIN*HH];
__device__ float g_w1[HH], g_w2[HH];
__device__ float g_u1[HH], g_u2[HH];
__device__ float g_v1[HH], g_v2[HH];
__device__ float g_psum[GGR*HH];
__device__ float g_pmax[GGR*HH];
__device__ int   g_cnt[GGR];

#define F4ACC(a,b) { (a).x+=(b).x; (a).y+=(b).y; (a).z+=(b).z; (a).w+=(b).w; }
#define F4FMA(a,s,m) { (a).x+=(s)*(m).x; (a).y+=(s)*(m).y; (a).z+=(s)*(m).z; (a).w+=(s)*(m).w; }

// ---------------- init ----------------
__global__ void init_zero() {
    int i = blockIdx.x*blockDim.x + threadIdx.x;
    int stride = gridDim.x*blockDim.x;
    for (int k=i; k<NN; k+=stride) g_deg[k]=0;
    for (int k=i; k<GGR*HH; k+=stride){ g_psum[k]=0.f; g_pmax[k]=0.f; }
    for (int k=i; k<GGR; k+=stride) g_cnt[k]=0;
}

// ---------------- CSR build ----------------
__global__ void deg_kernel(const int* __restrict__ dst) {
    int e = blockIdx.x*blockDim.x + threadIdx.x;
    if (e < EE) atomicAdd(&g_deg[dst[e]], 1);
}

__global__ void scan_kernel() {
    __shared__ int buf[1024];
    __shared__ int carry_s;
    int tid = threadIdx.x;
    if (tid==0) carry_s = 0;
    __syncthreads();
    for (int base=0; base<NN; base+=1024) {
        int idx = base + tid;
        int v = (idx<NN) ? g_deg[idx] : 0;
        buf[tid] = v;
        __syncthreads();
        for (int off=1; off<1024; off<<=1) {
            int t = (tid>=off) ? buf[tid-off] : 0;
            __syncthreads();
            buf[tid] += t;
            __syncthreads();
        }
        int incl = buf[tid];
        int carry = carry_s;
        __syncthreads();
        if (idx<NN) {
            int excl = carry + incl - v;
            g_rowptr[idx] = excl;
            g_fill[idx]   = excl;
            if (idx==NN-1) g_rowptr[NN] = carry + incl;
        }
        if (tid==1023) carry_s = carry + incl;
        __syncthreads();
    }
}

__global__ void fill_kernel(const int* __restrict__ src, const int* __restrict__ dst) {
    int e = blockIdx.x*blockDim.x + threadIdx.x;
    if (e < EE) {
        int d = dst[e];
        int pos = atomicAdd(&g_fill[d], 1);
        g_csr_src[pos] = src[e];
        g_csr_eid[pos] = e;
    }
}

// S[i,:] = sum of edge_attr over incoming edges (warp per node, lane = channel)
__global__ void S_kernel(const float* __restrict__ edge_attr) {
    int gw   = (blockIdx.x*blockDim.x + threadIdx.x) >> 5;
    int lane = threadIdx.x & 31;
    if (gw >= NN) return;
    int s = g_rowptr[gw], e = g_rowptr[gw+1];
    float acc = 0.f;
    for (int p=s; p<e; p++) {
        int eid = g_csr_eid[p];
        acc += edge_attr[eid*EIN + lane];
    }
    g_S[gw*EIN + lane] = acc;
}

// ---------------- tiny weight-product precompute ----------------
// M_X = WnX @ WuX ; T_X = We2l @ WeX ; w_X = be2l@WeX + beX + bnX
__global__ void tinyA(const float* __restrict__ Wn, const float* __restrict__ Wu,
                      const float* __restrict__ We, const float* __restrict__ We2l,
                      const float* __restrict__ be2l, const float* __restrict__ be,
                      const float* __restrict__ bn, int X) {
    int c = threadIdx.x, b = blockIdx.x;
    float* M = X ? g_M2 : g_M1;
    float* T = X ? g_T2 : g_T1;
    float* w = X ? g_w2 : g_w1;
    if (b < 128) {
        float a = 0.f;
        #pragma unroll 8
        for (int k=0;k<128;k++) a += Wn[b*128+k]*Wu[k*128+c];
        M[b*128+c] = a;
    } else if (b < 160) {
        int r = b - 128;
        float a = 0.f;
        #pragma unroll 8
        for (int k=0;k<128;k++) a += We2l[r*128+k]*We[k*128+c];
        T[r*128+c] = a;
    } else {
        float a = be[c] + bn[c];
        #pragma unroll 8
        for (int k=0;k<128;k++) a += be2l[k]*We[k*128+c];
        w[c] = a;
    }
}

// G_X = T_X @ WuX ; u_X = w_X @ WuX ; v_X = (bnX+beX) @ WuX + buX
__global__ void tinyB(const float* __restrict__ Wu, const float* __restrict__ bn,
                      const float* __restrict__ be, const float* __restrict__ bu, int X) {
    int c = threadIdx.x, b = blockIdx.x;
    const float* T = X ? g_T2 : g_T1;
    const float* w = X ? g_w2 : g_w1;
    float* Gm = X ? g_Gm2 : g_Gm1;
    float* u  = X ? g_u2  : g_u1;
    float* v  = X ? g_v2  : g_v1;
    if (b < 32) {
        float a = 0.f;
        #pragma unroll 8
        for (int k=0;k<128;k++) a += T[b*128+k]*Wu[k*128+c];
        Gm[b*128+c] = a;
    } else if (b == 32) {
        float a = 0.f;
        #pragma unroll 8
        for (int k=0;k<128;k++) a += w[k]*Wu[k*128+c];
        u[c] = a;
    } else {
        float a = bu[c];
        #pragma unroll 8
        for (int k=0;k<128;k++) a += (bn[k]+be[k])*Wu[k*128+c];
        v[c] = a;
    }
}

// D_X[i,:] = S[i,:] @ G_X + deg[i]*u_X + v_X
__global__ void D_kernel() {
    __shared__ float G1s[EIN*HH];
    __shared__ float G2s[EIN*HH];
    __shared__ float Ssh[EIN];
    int c = threadIdx.x;
    for (int k=c; k<EIN*HH; k+=128) { G1s[k]=g_Gm1[k]; G2s[k]=g_Gm2[k]; }
    float u1=g_u1[c], u2=g_u2[c], v1=g_v1[c], v2=g_v2[c];
    __syncthreads();
    for (int i=blockIdx.x; i<NN; i+=gridDim.x) {
        if (c<EIN) Ssh[c] = g_S[i*EIN+c];
        __syncthreads();
        float dg = (float)g_deg[i];
        float a1 = v1 + dg*u1, a2 = v2 + dg*u2;
        #pragma unroll
        for (int k=0;k<EIN;k++){ float s=Ssh[k]; a1 += s*G1s[k*HH+c]; a2 += s*G2s[k*HH+c]; }
        g_D1[i*HH+c] = a1;
        g_D2[i*HH+c] = a2;
        __syncthreads();
    }
}

// ---------------- fused (gather + GEMM + bias + relu) conv ----------------
// GATHER: hout = relu((A@h + h) @ M_which + D_which)
// !GATHER: hout = xin @ Mext + colbias      (h0 projection, no relu)
#define CONV_SMEM ((HH*HH + 64*HH)*4)

template<bool GATHER>
__global__ void __launch_bounds__(256, 2)
conv_gemm(const float* __restrict__ xin, const float* __restrict__ Mext,
          const float* __restrict__ colbias, int dstA, int which) {
    extern __shared__ float smem[];
    float* Msh = smem;            // [128][128]
    float* Gsh = smem + HH*HH;    // [64][128]

    const float* M;
    const float* hin;
    const float* D = nullptr;
    if (GATHER) {
        M   = which ? g_M2 : g_M1;
        D   = which ? g_D2 : g_D1;
        hin = dstA  ? g_hB : g_hA;
    } else {
        M = Mext; hin = xin;
    }
    float* hout = dstA ? g_hA : g_hB;

    int tid = threadIdx.x;
    {   // load M -> smem
        const float4* m4 = (const float4*)M;
        float4* s4 = (float4*)Msh;
        #pragma unroll
        for (int i=0;i<16;i++) s4[tid + 256*i] = m4[tid + 256*i];
    }
    int row0 = blockIdx.x * 64;
    int lane = tid & 31, wid = tid >> 5;

    if (GATHER) {
        // warp per node: g = h_i + sum_{j in N(i)} h_j, lane owns 4 channels
        for (int n = wid; n < 64; n += 8) {
            int i = row0 + n;
            float4 z = make_float4(0.f,0.f,0.f,0.f);
            float4 a0=z, a1=z, a2=z, a3=z;
            if (i < NN) {
                const float* hl = hin + lane*4;
                a0 = *(const float4*)(hl + i*HH);
                int s = g_rowptr[i], e = g_rowptr[i+1];
                int p = s;
                for (; p + 4 <= e; p += 4) {
                    int j0=g_csr_src[p], j1=g_csr_src[p+1], j2=g_csr_src[p+2], j3=g_csr_src[p+3];
                    float4 b0 = *(const float4*)(hl + j0*HH);
                    float4 b1 = *(const float4*)(hl + j1*HH);
                    float4 b2 = *(const float4*)(hl + j2*HH);
                    float4 b3 = *(const float4*)(hl + j3*HH);
                    F4ACC(a0,b0); F4ACC(a1,b1); F4ACC(a2,b2); F4ACC(a3,b3);
                }
                for (; p < e; p++) {
                    int j = g_csr_src[p];
                    float4 b = *(const float4*)(hl + j*HH);
                    F4ACC(a0,b);
                }
            }
            F4ACC(a0,a1); F4ACC(a2,a3); F4ACC(a0,a2);
            *(float4*)(Gsh + n*HH + lane*4) = a0;
        }
    } else {
        // straight copy of 64 input rows
        #pragma unroll
        for (int i=0;i<8;i++) {
            int idx = tid + 256*i;          // float4 index into Gsh
            int n = idx >> 5, c4 = idx & 31;
            int gi = row0 + n;
            float4 v = make_float4(0.f,0.f,0.f,0.f);
            if (gi < NN) v = ((const float4*)hin)[gi*32 + c4];
            ((float4*)Gsh)[idx] = v;
        }
    }
    __syncthreads();

    // GEMM: thread (lane, wid) -> cols lane*4..lane*4+3, rows wid*8..wid*8+7
    float4 acc[8];
    int tx = lane, ty = wid;
    if (GATHER) {
        #pragma unroll
        for (int r=0;r<8;r++) {
            int gi = row0 + ty*8 + r;
            acc[r] = (gi<NN) ? *(const float4*)(D + gi*HH + tx*4)
                             : make_float4(0.f,0.f,0.f,0.f);
        }
    } else {
        float4 cb = *(const float4*)(colbias + tx*4);
        #pragma unroll
        for (int r=0;r<8;r++) acc[r] = cb;
    }
    const float* Gb = Gsh + ty*8*HH;
    const float* Mc = Msh + tx*4;
    #pragma unroll 2
    for (int k=0;k<HH;k+=4) {
        float4 m0 = *(const float4*)(Mc + (k+0)*HH);
        float4 m1 = *(const float4*)(Mc + (k+1)*HH);
        float4 m2 = *(const float4*)(Mc + (k+2)*HH);
        float4 m3 = *(const float4*)(Mc + (k+3)*HH);
        #pragma unroll
        for (int r=0;r<8;r++) {
            float4 gv = *(const float4*)(Gb + r*HH + k);
            F4FMA(acc[r], gv.x, m0);
            F4FMA(acc[r], gv.y, m1);
            F4FMA(acc[r], gv.z, m2);
            F4FMA(acc[r], gv.w, m3);
        }
    }
    #pragma unroll
    for (int r=0;r<8;r++) {
        int gi = row0 + ty*8 + r;
        if (gi < NN) {
            float4 o = acc[r];
            if (GATHER) {
                o.x=fmaxf(o.x,0.f); o.y=fmaxf(o.y,0.f);
                o.z=fmaxf(o.z,0.f); o.w=fmaxf(o.w,0.f);
            }
            *(float4*)(hout + gi*HH + tx*4) = o;
        }
    }
}

// ---------------- pooling (batch is sorted -> run-based partial reduce) ----------------
__global__ void pool_kernel(const int* __restrict__ batch) {
    __shared__ int bsh[256];
    int c = threadIdx.x;
    int s = blockIdx.x*256;
    int nloc = NN - s; if (nloc > 256) nloc = 256;
    for (int i=c; i<nloc; i+=128) bsh[i] = batch[s+i];
    __syncthreads();
    const float* h = g_hA;
    float sum=0.f, mx=0.f; int cnt=0;
    int cur = bsh[0];
    for (int i=0;i<nloc;i++) {
        int g = bsh[i];
        if (g != cur) {
            atomicAdd(&g_psum[cur*HH+c], sum);
            atomicMax((unsigned int*)&g_pmax[cur*HH+c], __float_as_uint(mx));
            if (c==0) atomicAdd(&g_cnt[cur], cnt);
            cur=g; sum=0.f; mx=0.f; cnt=0;
        }
        float v = h[(size_t)(s+i)*HH + c];
        sum += v; mx = fmaxf(mx, v); cnt++;
    }
    atomicAdd(&g_psum[cur*HH+c], sum);
    atomicMax((unsigned int*)&g_pmax[cur*HH+c], __float_as_uint(mx));
    if (c==0) atomicAdd(&g_cnt[cur], cnt);
}

// ---------------- readout head ----------------
__global__ void head_kernel(const float* __restrict__ Wm1, const float* __restrict__ bm1,
                            const float* __restrict__ Wm2, const float* __restrict__ bm2,
                            float* __restrict__ out) {
    __shared__ float pooled[2*HH];
    __shared__ float z1[HH];
    int g = blockIdx.x, c = threadIdx.x;
    float denom = fmaxf((float)g_cnt[g], 1.f);
    pooled[c]    = g_psum[g*HH+c] / denom;
    pooled[HH+c] = g_pmax[g*HH+c];
    __syncthreads();
    float a = bm1[c];
    #pragma unroll 8
    for (int k=0;k<2*HH;k++) a += pooled[k]*Wm1[k*HH+c];
    z1[c] = fmaxf(a, 0.f);
    __syncthreads();
    if (c < 2) {
        float o = bm2[c];
        for (int k=0;k<HH;k++) o += z1[k]*Wm2[k*2+c];
        out[g*2+c] = 1.f/(1.f+expf(-o));
    }
}

// ---------------- launch ----------------
extern "C" void kernel_launch(void* const* d_in, const int* in_sizes, int n_in,
                              void* d_out, int out_size) {
    const float* x         = (const float*)d_in[0];
    const float* edge_attr = (const float*)d_in[1];
    const int*   ei        = (const int*)  d_in[2];
    const int*   batch     = (const int*)  d_in[3];
    const float* Wn2l = (const float*)d_in[4];
    const float* bn2l = (const float*)d_in[5];
    const float* We2l = (const float*)d_in[6];
    const float* be2l = (const float*)d_in[7];
    const float* Wn1  = (const float*)d_in[8];
    const float* bn1  = (const float*)d_in[9];
    const float* We1  = (const float*)d_in[10];
    const float* be1  = (const float*)d_in[11];
    const float* Wu1  = (const float*)d_in[12];
    const float* bu1  = (const float*)d_in[13];
    const float* Wn2  = (const float*)d_in[14];
    const float* bn2  = (const float*)d_in[15];
    const float* We2  = (const float*)d_in[16];
    const float* be2  = (const float*)d_in[17];
    const float* Wu2  = (const float*)d_in[18];
    const float* bu2  = (const float*)d_in[19];
    const float* Wm1  = (const float*)d_in[20];
    const float* bm1  = (const float*)d_in[21];
    const float* Wm2  = (const float*)d_in[22];
    const float* bm2  = (const float*)d_in[23];
    float* out = (float*)d_out;

    const int* src = ei;
    const int* dst = ei + EE;

    cudaFuncSetAttribute(conv_gemm<true>,  cudaFuncAttributeMaxDynamicSharedMemorySize, CONV_SMEM);
    cudaFuncSetAttribute(conv_gemm<false>, cudaFuncAttributeMaxDynamicSharedMemorySize, CONV_SMEM);

    init_zero<<<80, 512>>>();
    deg_kernel<<<(EE+255)/256, 256>>>(dst);
    scan_kernel<<<1, 1024>>>();
    fill_kernel<<<(EE+255)/256, 256>>>(src, dst);
    S_kernel<<<(NN*32)/256, 256>>>(edge_attr);

    tinyA<<<161, 128>>>(Wn1, Wu1, We1, We2l, be2l, be1, bn1, 0);
    tinyA<<<161, 128>>>(Wn2, Wu2, We2, We2l, be2l, be2, bn2, 1);
    tinyB<<<34, 128>>>(Wu1, bn1, be1, bu1, 0);
    tinyB<<<34, 128>>>(Wu2, bn2, be2, bu2, 1);
    D_kernel<<<296, 128>>>();

    const int CG = (NN + 63) / 64;   // 313 blocks
    // h0 = x @ Wn2l + bn2l  -> g_hA
    conv_gemm<false><<<CG, 256, CONV_SMEM>>>(x, Wn2l, bn2l, /*dstA=*/1, 0);
    // 3 x (conv1, conv2)
    conv_gemm<true><<<CG, 256, CONV_SMEM>>>(nullptr, nullptr, nullptr, 0, 0); // A->B, M1/D1
    conv_gemm<true><<<CG, 256, CONV_SMEM>>>(nullptr, nullptr, nullptr, 1, 1); // B->A, M2/D2
    conv_gemm<true><<<CG, 256, CONV_SMEM>>>(nullptr, nullptr, nullptr, 0, 0);
    conv_gemm<true><<<CG, 256, CONV_SMEM>>>(nullptr, nullptr, nullptr, 1, 1);
    conv_gemm<true><<<CG, 256, CONV_SMEM>>>(nullptr, nullptr, nullptr, 0, 0);
    conv_gemm<true><<<CG, 256, CONV_SMEM>>>(nullptr, nullptr, nullptr, 1, 1);

    pool_kernel<<<(NN+255)/256, 128>>>(batch);
    head_kernel<<<GGR, 128>>>(Wm1, bm1, Wm2, bm2, out);
}

// round 4
// speedup vs baseline: 1.0242x; 1.0242x over previous
#include <cuda_runtime.h>
#include <math.h>

#define NN 20000
#define EE 640000
#define EPAD 800000        // CSR capacity with rows padded to multiples of 8
#define GGR 64
#define HH 128
#define EIN 32
#define NT ((NN + 63) / 64)    // 313 tiles of 64 nodes
#define NBLK 148
#define NSB ((NN + 255) / 256) // 79 scan blocks

// ---------------- scratch (static device globals; no allocation) ----------------
__device__ float g_hA[(NN+1)*HH];   // row NN = zero sentinel
__device__ float g_hB[(NN+1)*HH];
__device__ float g_D1[NN*HH];
__device__ float g_D2[NN*HH];
__device__ float g_S[NN*EIN];
__device__ int   g_deg[NN];
__device__ int   g_rowptr[NN+1];    // padded exclusive scan
__device__ int   g_fill[NN];
__device__ int2  g_csr[EPAD];       // .x = src node (NN = sentinel), .y = edge id
__device__ int   g_tmp[NN];
__device__ int   g_bsum[NSB];
__device__ int   g_boff[NSB];
__device__ float g_M1[HH*HH], g_M2[HH*HH];
__device__ float g_T1[EIN*HH], g_T2[EIN*HH];
__device__ float g_Gm1[EIN*HH], g_Gm2[EIN*HH];
__device__ float g_w1[HH], g_w2[HH];
__device__ float g_u1[HH], g_u2[HH];
__device__ float g_v1[HH], g_v2[HH];
__device__ float g_psum[GGR*HH];
__device__ float g_pmax[GGR*HH];
__device__ int   g_cnt[GGR];

#define F4ACC(a,b) { (a).x+=(b).x; (a).y+=(b).y; (a).z+=(b).z; (a).w+=(b).w; }
#define F4FMA(a,s,m) { (a).x+=(s)*(m).x; (a).y+=(s)*(m).y; (a).z+=(s)*(m).z; (a).w+=(s)*(m).w; }

// ---------------- init ----------------
__global__ void init_zero() {
    int i = blockIdx.x*blockDim.x + threadIdx.x;
    int stride = gridDim.x*blockDim.x;
    for (int k=i; k<NN; k+=stride) g_deg[k]=0;
    for (int k=i; k<GGR*HH; k+=stride){ g_psum[k]=0.f; g_pmax[k]=0.f; }
    for (int k=i; k<GGR; k+=stride) g_cnt[k]=0;
    for (int k=i; k<HH; k+=stride){ g_hA[NN*HH+k]=0.f; g_hB[NN*HH+k]=0.f; }
    int2 sent = make_int2(NN, 0);
    for (int k=i; k<EPAD; k+=stride) g_csr[k] = sent;
}

// ---------------- CSR build ----------------
__global__ void deg_kernel(const int* __restrict__ dst) {
    int e = blockIdx.x*blockDim.x + threadIdx.x;
    if (e < EE) atomicAdd(&g_deg[dst[e]], 1);
}

// 3-phase scan of padded degrees
__global__ void scan1_kernel() {
    __shared__ int ws[8];
    int b = blockIdx.x, t = threadIdx.x;
    int i = b*256 + t;
    int v = (i < NN) ? ((g_deg[i] + 7) & ~7) : 0;
    int x = v;
    #pragma unroll
    for (int o=1;o<32;o<<=1){ int y=__shfl_up_sync(0xFFFFFFFFu,x,o); if ((t&31)>=o) x+=y; }
    if ((t&31)==31) ws[t>>5]=x;
    __syncthreads();
    if (t < 8) {
        int s = ws[t];
        #pragma unroll
        for (int o=1;o<8;o<<=1){ int y=__shfl_up_sync(0xFFu,s,o); if (t>=o) s+=y; }
        ws[t] = s;
    }
    __syncthreads();
    int add = (t>=32) ? ws[(t>>5)-1] : 0;
    int incl = x + add;
    if (i < NN) g_tmp[i] = incl;
    if (t == 255) g_bsum[b] = incl;
}

__global__ void scan2_kernel() {
    __shared__ int ws[4];
    int t = threadIdx.x;
    int v = (t < NSB) ? g_bsum[t] : 0;
    int x = v;
    #pragma unroll
    for (int o=1;o<32;o<<=1){ int y=__shfl_up_sync(0xFFFFFFFFu,x,o); if ((t&31)>=o) x+=y; }
    if ((t&31)==31) ws[t>>5]=x;
    __syncthreads();
    int add = 0;
    if (t>=32) add = ws[0];
    if (t>=64) add += ws[1];
    if (t>=96) add += ws[2];
    if (t < NSB) g_boff[t] = x + add - v;
}

__global__ void scan3_kernel() {
    int i = blockIdx.x*256 + threadIdx.x;
    if (i < NN) {
        int v = (g_deg[i] + 7) & ~7;
        int excl = g_boff[blockIdx.x] + g_tmp[i] - v;
        g_rowptr[i] = excl;
        g_fill[i]   = excl;
        if (i == NN-1) g_rowptr[NN] = excl + v;
    }
}

__global__ void fill_kernel(const int* __restrict__ src, const int* __restrict__ dst) {
    int e = blockIdx.x*blockDim.x + threadIdx.x;
    if (e < EE) {
        int d = dst[e];
        int pos = atomicAdd(&g_fill[d], 1);
        g_csr[pos] = make_int2(src[e], e);
    }
}

// S[i,:] = sum of edge_attr over real incoming edges (warp per node, lane = channel)
__global__ void S_kernel(const float* __restrict__ edge_attr) {
    int gw   = (blockIdx.x*blockDim.x + threadIdx.x) >> 5;
    int lane = threadIdx.x & 31;
    if (gw >= NN) return;
    int s = g_rowptr[gw], d = g_deg[gw];
    float a0=0.f, a1=0.f, a2=0.f, a3=0.f;
    int p = s;
    for (; p + 4 <= s + d; p += 4) {
        int e0 = g_csr[p].y, e1 = g_csr[p+1].y, e2 = g_csr[p+2].y, e3 = g_csr[p+3].y;
        a0 += edge_attr[e0*EIN + lane];
        a1 += edge_attr[e1*EIN + lane];
        a2 += edge_attr[e2*EIN + lane];
        a3 += edge_attr[e3*EIN + lane];
    }
    for (; p < s + d; p++) a0 += edge_attr[g_csr[p].y*EIN + lane];
    g_S[gw*EIN + lane] = (a0+a1)+(a2+a3);
}

// ---------------- tiny weight-product precompute ----------------
__global__ void tinyA(const float* __restrict__ Wn, const float* __restrict__ Wu,
                      const float* __restrict__ We, const float* __restrict__ We2l,
                      const float* __restrict__ be2l, const float* __restrict__ be,
                      const float* __restrict__ bn, int X) {
    int c = threadIdx.x, b = blockIdx.x;
    float* M = X ? g_M2 : g_M1;
    float* T = X ? g_T2 : g_T1;
    float* w = X ? g_w2 : g_w1;
    if (b < 128) {
        float a = 0.f;
        #pragma unroll 8
        for (int k=0;k<128;k++) a += Wn[b*128+k]*Wu[k*128+c];
        M[b*128+c] = a;
    } else if (b < 160) {
        int r = b - 128;
        float a = 0.f;
        #pragma unroll 8
        for (int k=0;k<128;k++) a += We2l[r*128+k]*We[k*128+c];
        T[r*128+c] = a;
    } else {
        float a = be[c] + bn[c];
        #pragma unroll 8
        for (int k=0;k<128;k++) a += be2l[k]*We[k*128+c];
        w[c] = a;
    }
}

__global__ void tinyB(const float* __restrict__ Wu, const float* __restrict__ bn,
                      const float* __restrict__ be, const float* __restrict__ bu, int X) {
    int c = threadIdx.x, b = blockIdx.x;
    const float* T = X ? g_T2 : g_T1;
    const float* w = X ? g_w2 : g_w1;
    float* Gm = X ? g_Gm2 : g_Gm1;
    float* u  = X ? g_u2  : g_u1;
    float* v  = X ? g_v2  : g_v1;
    if (b < 32) {
        float a = 0.f;
        #pragma unroll 8
        for (int k=0;k<128;k++) a += T[b*128+k]*Wu[k*128+c];
        Gm[b*128+c] = a;
    } else if (b == 32) {
        float a = 0.f;
        #pragma unroll 8
        for (int k=0;k<128;k++) a += w[k]*Wu[k*128+c];
        u[c] = a;
    } else {
        float a = bu[c];
        #pragma unroll 8
        for (int k=0;k<128;k++) a += (bn[k]+be[k])*Wu[k*128+c];
        v[c] = a;
    }
}

// D_X[i,:] = S[i,:] @ G_X + deg[i]*u_X + v_X
__global__ void D_kernel() {
    __shared__ float G1s[EIN*HH];
    __shared__ float G2s[EIN*HH];
    __shared__ float Ssh[EIN];
    int c = threadIdx.x;
    for (int k=c; k<EIN*HH; k+=128) { G1s[k]=g_Gm1[k]; G2s[k]=g_Gm2[k]; }
    float u1=g_u1[c], u2=g_u2[c], v1=g_v1[c], v2=g_v2[c];
    __syncthreads();
    for (int i=blockIdx.x; i<NN; i+=gridDim.x) {
        if (c<EIN) Ssh[c] = g_S[i*EIN+c];
        __syncthreads();
        float dg = (float)g_deg[i];
        float a1 = v1 + dg*u1, a2 = v2 + dg*u2;
        #pragma unroll
        for (int k=0;k<EIN;k++){ float s=Ssh[k]; a1 += s*G1s[k*HH+c]; a2 += s*G2s[k*HH+c]; }
        g_D1[i*HH+c] = a1;
        g_D2[i*HH+c] = a2;
        __syncthreads();
    }
}

// ---------------- warp-specialized persistent fused conv ----------------
// producers (warps 0-7): G[tile] = (A+I) h  (64 rows, double buffered)
// consumers (warps 8-11): hout = relu(G @ M + D)   (or x-proj: G @ M + bias, no relu)
#define CSMEM ((HH*HH + 2*64*HH)*4)   // 64KB M + 2x32KB G = 128KB

#define BARSYNC(id) asm volatile("bar.sync %0, 384;" :: "r"(id) : "memory")
#define BARARR(id)  asm volatile("bar.arrive %0, 384;" :: "r"(id) : "memory")

template<bool PROJ>
__global__ void __launch_bounds__(384, 1)
conv_ws(const float* __restrict__ xin, const float* __restrict__ Mext,
        const float* __restrict__ bias, int which, int dstA)
{
    extern __shared__ float smem[];
    float* Ms  = smem;                 // [128][128]
    float* Gs0 = smem + HH*HH;         // [64][128]
    float* Gs1 = Gs0 + 64*HH;

    const float* M   = PROJ ? Mext : (which ? g_M2 : g_M1);
    const float* hin = PROJ ? xin  : (dstA ? g_hB : g_hA);
    const float* D   = PROJ ? (const float*)nullptr : (which ? g_D2 : g_D1);
    float* hout = dstA ? g_hA : g_hB;

    int tid = threadIdx.x;
    for (int i = tid; i < HH*HH/4; i += 384)
        ((float4*)Ms)[i] = ((const float4*)M)[i];
    __syncthreads();

    int wid = tid >> 5, lane = tid & 31;

    if (wid < 8) {
        // ---------------- producer ----------------
        int idx = 0;
        for (int tile = blockIdx.x; tile < NT; tile += gridDim.x, idx++) {
            int bufb = idx & 1;
            if (idx >= 2) BARSYNC(3 + bufb);
            float* G = bufb ? Gs1 : Gs0;
            int row0 = tile * 64;
            for (int n = wid; n < 64; n += 8) {
                int i = row0 + n;
                float4 z = make_float4(0.f,0.f,0.f,0.f);
                float4 a0=z,a1=z,a2=z,a3=z,a4=z,a5=z,a6=z,a7=z;
                if (i < NN) {
                    const float* hl = hin + lane*4;
                    a0 = *(const float4*)(hl + i*HH);
                    if (!PROJ) {
                        int s = g_rowptr[i], e = g_rowptr[i+1];
                        for (int p = s; p < e; p += 8) {
                            const int4* cp = (const int4*)(g_csr + p);  // 8 int2 entries
                            int4 c0 = cp[0], c1 = cp[1], c2 = cp[2], c3 = cp[3];
                            float4 b0 = *(const float4*)(hl + c0.x*HH);
                            float4 b1 = *(const float4*)(hl + c0.z*HH);
                            float4 b2 = *(const float4*)(hl + c1.x*HH);
                            float4 b3 = *(const float4*)(hl + c1.z*HH);
                            float4 b4 = *(const float4*)(hl + c2.x*HH);
                            float4 b5 = *(const float4*)(hl + c2.z*HH);
                            float4 b6 = *(const float4*)(hl + c3.x*HH);
                            float4 b7 = *(const float4*)(hl + c3.z*HH);
                            F4ACC(a0,b0); F4ACC(a1,b1); F4ACC(a2,b2); F4ACC(a3,b3);
                            F4ACC(a4,b4); F4ACC(a5,b5); F4ACC(a6,b6); F4ACC(a7,b7);
                        }
                    }
                }
                F4ACC(a0,a1); F4ACC(a2,a3); F4ACC(a4,a5); F4ACC(a6,a7);
                F4ACC(a0,a2); F4ACC(a4,a6); F4ACC(a0,a4);
                *(float4*)(G + n*HH + lane*4) = a0;
            }
            BARARR(1 + bufb);
        }
    } else {
        // ---------------- consumer ----------------
        int ct = tid - 256;            // 0..127
        int tx = ct & 15, ty = ct >> 4;
        int colb = tx * 8;
        int idx = 0;
        for (int tile = blockIdx.x; tile < NT; tile += gridDim.x, idx++) {
            int bufb = idx & 1;
            int row0 = tile * 64;
            float4 acc[8][2];
            if (PROJ) {
                float4 cb0 = *(const float4*)(bias + colb);
                float4 cb1 = *(const float4*)(bias + colb + 4);
                #pragma unroll
                for (int r=0;r<8;r++){ acc[r][0]=cb0; acc[r][1]=cb1; }
            } else {
                #pragma unroll
                for (int r=0;r<8;r++) {
                    int gi = row0 + ty*8 + r;
                    if (gi < NN) {
                        acc[r][0] = *(const float4*)(D + gi*HH + colb);
                        acc[r][1] = *(const float4*)(D + gi*HH + colb + 4);
                    } else {
                        acc[r][0] = make_float4(0.f,0.f,0.f,0.f);
                        acc[r][1] = make_float4(0.f,0.f,0.f,0.f);
                    }
                }
            }
            BARSYNC(1 + bufb);
            const float* G = (bufb ? Gs1 : Gs0) + ty*8*HH;
            #pragma unroll 2
            for (int k0 = 0; k0 < HH; k0 += 4) {
                float4 a[8];
                #pragma unroll
                for (int r=0;r<8;r++) a[r] = *(const float4*)(G + r*HH + k0);
                #pragma unroll
                for (int kk=0;kk<4;kk++) {
                    float4 b0 = *(const float4*)(Ms + (k0+kk)*HH + colb);
                    float4 b1 = *(const float4*)(Ms + (k0+kk)*HH + colb + 4);
                    #pragma unroll
                    for (int r=0;r<8;r++) {
                        float av = (kk==0)?a[r].x : (kk==1)?a[r].y : (kk==2)?a[r].z : a[r].w;
                        F4FMA(acc[r][0], av, b0);
                        F4FMA(acc[r][1], av, b1);
                    }
                }
            }
            BARARR(3 + bufb);
            #pragma unroll
            for (int r=0;r<8;r++) {
                int gi = row0 + ty*8 + r;
                if (gi < NN) {
                    float4 o0 = acc[r][0], o1 = acc[r][1];
                    if (!PROJ) {
                        o0.x=fmaxf(o0.x,0.f); o0.y=fmaxf(o0.y,0.f);
                        o0.z=fmaxf(o0.z,0.f); o0.w=fmaxf(o0.w,0.f);
                        o1.x=fmaxf(o1.x,0.f); o1.y=fmaxf(o1.y,0.f);
                        o1.z=fmaxf(o1.z,0.f); o1.w=fmaxf(o1.w,0.f);
                    }
                    *(float4*)(hout + gi*HH + colb)     = o0;
                    *(float4*)(hout + gi*HH + colb + 4) = o1;
                }
            }
        }
    }
}

// ---------------- pooling (batch sorted -> run-based partial reduce) ----------------
__global__ void pool_kernel(const int* __restrict__ batch) {
    __shared__ int bsh[128];
    int c = threadIdx.x;
    int s = blockIdx.x*128;
    int nloc = NN - s; if (nloc > 128) nloc = 128;
    for (int i=c; i<nloc; i+=128) bsh[i] = batch[s+i];
    __syncthreads();
    const float* h = g_hA;
    float sum=0.f, mx=0.f; int cnt=0;
    int cur = bsh[0];
    for (int i=0;i<nloc;i++) {
        int g = bsh[i];
        if (g != cur) {
            atomicAdd(&g_psum[cur*HH+c], sum);
            atomicMax((unsigned int*)&g_pmax[cur*HH+c], __float_as_uint(mx));
            if (c==0) atomicAdd(&g_cnt[cur], cnt);
            cur=g; sum=0.f; mx=0.f; cnt=0;
        }
        float v = h[(s+i)*HH + c];
        sum += v; mx = fmaxf(mx, v); cnt++;
    }
    atomicAdd(&g_psum[cur*HH+c], sum);
    atomicMax((unsigned int*)&g_pmax[cur*HH+c], __float_as_uint(mx));
    if (c==0) atomicAdd(&g_cnt[cur], cnt);
}

// ---------------- readout head ----------------
__global__ void head_kernel(const float* __restrict__ Wm1, const float* __restrict__ bm1,
                            const float* __restrict__ Wm2, const float* __restrict__ bm2,
                            float* __restrict__ out) {
    __shared__ float pooled[2*HH];
    __shared__ float z1[HH];
    int g = blockIdx.x, c = threadIdx.x;
    float denom = fmaxf((float)g_cnt[g], 1.f);
    pooled[c]    = g_psum[g*HH+c] / denom;
    pooled[HH+c] = g_pmax[g*HH+c];
    __syncthreads();
    float a = bm1[c];
    #pragma unroll 8
    for (int k=0;k<2*HH;k++) a += pooled[k]*Wm1[k*HH+c];
    z1[c] = fmaxf(a, 0.f);
    __syncthreads();
    if (c < 2) {
        float o = bm2[c];
        for (int k=0;k<HH;k++) o += z1[k]*Wm2[k*2+c];
        out[g*2+c] = 1.f/(1.f+expf(-o));
    }
}

// ---------------- launch ----------------
extern "C" void kernel_launch(void* const* d_in, const int* in_sizes, int n_in,
                              void* d_out, int out_size) {
    const float* x         = (const float*)d_in[0];
    const float* edge_attr = (const float*)d_in[1];
    const int*   ei        = (const int*)  d_in[2];
    const int*   batch     = (const int*)  d_in[3];
    const float* Wn2l = (const float*)d_in[4];
    const float* bn2l = (const float*)d_in[5];
    const float* We2l = (const float*)d_in[6];
    const float* be2l = (const float*)d_in[7];
    const float* Wn1  = (const float*)d_in[8];
    const float* bn1  = (const float*)d_in[9];
    const float* We1  = (const float*)d_in[10];
    const float* be1  = (const float*)d_in[11];
    const float* Wu1  = (const float*)d_in[12];
    const float* bu1  = (const float*)d_in[13];
    const float* Wn2  = (const float*)d_in[14];
    const float* bn2  = (const float*)d_in[15];
    const float* We2  = (const float*)d_in[16];
    const float* be2  = (const float*)d_in[17];
    const float* Wu2  = (const float*)d_in[18];
    const float* bu2  = (const float*)d_in[19];
    const float* Wm1  = (const float*)d_in[20];
    const float* bm1  = (const float*)d_in[21];
    const float* Wm2  = (const float*)d_in[22];
    const float* bm2  = (const float*)d_in[23];
    float* out = (float*)d_out;

    const int* src = ei;
    const int* dst = ei + EE;

    cudaFuncSetAttribute(conv_ws<true>,  cudaFuncAttributeMaxDynamicSharedMemorySize, CSMEM);
    cudaFuncSetAttribute(conv_ws<false>, cudaFuncAttributeMaxDynamicSharedMemorySize, CSMEM);

    init_zero<<<400, 256>>>();
    deg_kernel<<<(EE+255)/256, 256>>>(dst);
    scan1_kernel<<<NSB, 256>>>();
    // projection (independent of CSR) — placed early
    conv_ws<true><<<NBLK, 384, CSMEM>>>(x, Wn2l, bn2l, 0, /*dstA=*/1);
    scan2_kernel<<<1, 128>>>();
    scan3_kernel<<<NSB, 256>>>();
    fill_kernel<<<(EE+255)/256, 256>>>(src, dst);
    S_kernel<<<(NN*32)/256, 256>>>(edge_attr);

    tinyA<<<161, 128>>>(Wn1, Wu1, We1, We2l, be2l, be1, bn1, 0);
    tinyA<<<161, 128>>>(Wn2, Wu2, We2, We2l, be2l, be2, bn2, 1);
    tinyB<<<34, 128>>>(Wu1, bn1, be1, bu1, 0);
    tinyB<<<34, 128>>>(Wu2, bn2, be2, bu2, 1);
    D_kernel<<<296, 128>>>();

    // 3 x (conv1, conv2): ping-pong hA <-> hB, final result in hA
    conv_ws<false><<<NBLK, 384, CSMEM>>>(nullptr, nullptr, nullptr, 0, 0); // A->B
    conv_ws<false><<<NBLK, 384, CSMEM>>>(nullptr, nullptr, nullptr, 1, 1); // B->A
    conv_ws<false><<<NBLK, 384, CSMEM>>>(nullptr, nullptr, nullptr, 0, 0);
    conv_ws<false><<<NBLK, 384, CSMEM>>>(nullptr, nullptr, nullptr, 1, 1);
    conv_ws<false><<<NBLK, 384, CSMEM>>>(nullptr, nullptr, nullptr, 0, 0);
    conv_ws<false><<<NBLK, 384, CSMEM>>>(nullptr, nullptr, nullptr, 1, 1);

    pool_kernel<<<(NN+127)/128, 128>>>(batch);
    head_kernel<<<GGR, 128>>>(Wm1, bm1, Wm2, bm2, out);
}

// round 5
// speedup vs baseline: 1.2732x; 1.2431x over previous
#include <cuda_runtime.h>
#include <math.h>

#define NN 20000
#define EE 640000
#define EPAD 800000        // CSR capacity with rows padded to multiples of 8
#define GGR 64
#define HH 128
#define EIN 32
#define TR 32                  // rows per conv tile
#define NT2 ((NN + TR - 1) / TR)   // 625 tiles
#define NBLK 148
#define NSB ((NN + 255) / 256) // 79 scan blocks

// ---------------- scratch (static device globals; no allocation) ----------------
__device__ float g_hA[(NN+1)*HH];   // row NN = zero sentinel
__device__ float g_hB[(NN+1)*HH];
__device__ float g_D1[NN*HH];
__device__ float g_D2[NN*HH];
__device__ float g_S[NN*EIN];
__device__ int   g_deg[NN];
__device__ int   g_rowptr[NN+1];    // padded exclusive scan
__device__ int   g_fill[NN];
__device__ int2  g_csr[EPAD];       // .x = src node (NN = sentinel), .y = edge id
__device__ int   g_tmp[NN];
__device__ int   g_bsum[NSB];
__device__ int   g_boff[NSB];
__device__ float g_M1[HH*HH], g_M2[HH*HH];
__device__ float g_T1[EIN*HH], g_T2[EIN*HH];
__device__ float g_Gm1[EIN*HH], g_Gm2[EIN*HH];
__device__ float g_w1[HH], g_w2[HH];
__device__ float g_u1[HH], g_u2[HH];
__device__ float g_v1[HH], g_v2[HH];
__device__ float g_psum[GGR*HH];
__device__ float g_pmax[GGR*HH];
__device__ int   g_cnt[GGR];

#define F4ACC(a,b) { (a).x+=(b).x; (a).y+=(b).y; (a).z+=(b).z; (a).w+=(b).w; }
#define F4FMA(a,s,m) { (a).x+=(s)*(m).x; (a).y+=(s)*(m).y; (a).z+=(s)*(m).z; (a).w+=(s)*(m).w; }

// ---------------- init ----------------
__global__ void init_zero() {
    int i = blockIdx.x*blockDim.x + threadIdx.x;
    int stride = gridDim.x*blockDim.x;
    for (int k=i; k<NN; k+=stride) g_deg[k]=0;
    for (int k=i; k<GGR*HH; k+=stride){ g_psum[k]=0.f; g_pmax[k]=0.f; }
    for (int k=i; k<GGR; k+=stride) g_cnt[k]=0;
    for (int k=i; k<HH; k+=stride){ g_hA[NN*HH+k]=0.f; g_hB[NN*HH+k]=0.f; }
}

// ---------------- CSR build ----------------
__global__ void deg_kernel(const int* __restrict__ dst) {
    int e = blockIdx.x*blockDim.x + threadIdx.x;
    if (e < EE) atomicAdd(&g_deg[dst[e]], 1);
}

// 3-phase scan of padded degrees
__global__ void scan1_kernel() {
    __shared__ int ws[8];
    int b = blockIdx.x, t = threadIdx.x;
    int i = b*256 + t;
    int v = (i < NN) ? ((g_deg[i] + 7) & ~7) : 0;
    int x = v;
    #pragma unroll
    for (int o=1;o<32;o<<=1){ int y=__shfl_up_sync(0xFFFFFFFFu,x,o); if ((t&31)>=o) x+=y; }
    if ((t&31)==31) ws[t>>5]=x;
    __syncthreads();
    if (t < 8) {
        int s = ws[t];
        #pragma unroll
        for (int o=1;o<8;o<<=1){ int y=__shfl_up_sync(0xFFu,s,o); if (t>=o) s+=y; }
        ws[t] = s;
    }
    __syncthreads();
    int add = (t>=32) ? ws[(t>>5)-1] : 0;
    int incl = x + add;
    if (i < NN) g_tmp[i] = incl;
    if (t == 255) g_bsum[b] = incl;
}

__global__ void scan2_kernel() {
    __shared__ int ws[4];
    int t = threadIdx.x;
    int v = (t < NSB) ? g_bsum[t] : 0;
    int x = v;
    #pragma unroll
    for (int o=1;o<32;o<<=1){ int y=__shfl_up_sync(0xFFFFFFFFu,x,o); if ((t&31)>=o) x+=y; }
    if ((t&31)==31) ws[t>>5]=x;
    __syncthreads();
    int add = 0;
    if (t>=32) add = ws[0];
    if (t>=64) add += ws[1];
    if (t>=96) add += ws[2];
    if (t < NSB) g_boff[t] = x + add - v;
}

__global__ void scan3_kernel() {
    int i = blockIdx.x*256 + threadIdx.x;
    if (i < NN) {
        int v = (g_deg[i] + 7) & ~7;
        int excl = g_boff[blockIdx.x] + g_tmp[i] - v;
        g_rowptr[i] = excl;
        g_fill[i]   = excl;
        if (i == NN-1) g_rowptr[NN] = excl + v;
    }
}

__global__ void fill_kernel(const int* __restrict__ src, const int* __restrict__ dst) {
    int e = blockIdx.x*blockDim.x + threadIdx.x;
    if (e < EE) {
        int d = dst[e];
        int pos = atomicAdd(&g_fill[d], 1);
        g_csr[pos] = make_int2(src[e], e);
    }
}

// write sentinel entries only into each row's padding region
__global__ void pad_kernel() {
    int i = blockIdx.x*blockDim.x + threadIdx.x;
    if (i < NN) {
        int p = g_fill[i];            // rowptr[i] + deg[i]
        int end = g_rowptr[i+1];
        int2 s = make_int2(NN, 0);
        for (; p < end; p++) g_csr[p] = s;
    }
}

// S[i,:] = sum of edge_attr over real incoming edges (warp per node, lane = channel)
__global__ void S_kernel(const float* __restrict__ edge_attr) {
    int gw   = (blockIdx.x*blockDim.x + threadIdx.x) >> 5;
    int lane = threadIdx.x & 31;
    if (gw >= NN) return;
    int s = g_rowptr[gw], d = g_deg[gw];
    float a0=0.f, a1=0.f, a2=0.f, a3=0.f;
    int p = s;
    for (; p + 4 <= s + d; p += 4) {
        int e0 = g_csr[p].y, e1 = g_csr[p+1].y, e2 = g_csr[p+2].y, e3 = g_csr[p+3].y;
        a0 += edge_attr[e0*EIN + lane];
        a1 += edge_attr[e1*EIN + lane];
        a2 += edge_attr[e2*EIN + lane];
        a3 += edge_attr[e3*EIN + lane];
    }
    for (; p < s + d; p++) a0 += edge_attr[g_csr[p].y*EIN + lane];
    g_S[gw*EIN + lane] = (a0+a1)+(a2+a3);
}

// ---------------- tiny weight-product precompute ----------------
__global__ void tinyA(const float* __restrict__ Wn, const float* __restrict__ Wu,
                      const float* __restrict__ We, const float* __restrict__ We2l,
                      const float* __restrict__ be2l, const float* __restrict__ be,
                      const float* __restrict__ bn, int X) {
    int c = threadIdx.x, b = blockIdx.x;
    float* M = X ? g_M2 : g_M1;
    float* T = X ? g_T2 : g_T1;
    float* w = X ? g_w2 : g_w1;
    if (b < 128) {
        float a = 0.f;
        #pragma unroll 8
        for (int k=0;k<128;k++) a += Wn[b*128+k]*Wu[k*128+c];
        M[b*128+c] = a;
    } else if (b < 160) {
        int r = b - 128;
        float a = 0.f;
        #pragma unroll 8
        for (int k=0;k<128;k++) a += We2l[r*128+k]*We[k*128+c];
        T[r*128+c] = a;
    } else {
        float a = be[c] + bn[c];
        #pragma unroll 8
        for (int k=0;k<128;k++) a += be2l[k]*We[k*128+c];
        w[c] = a;
    }
}

__global__ void tinyB(const float* __restrict__ Wu, const float* __restrict__ bn,
                      const float* __restrict__ be, const float* __restrict__ bu, int X) {
    int c = threadIdx.x, b = blockIdx.x;
    const float* T = X ? g_T2 : g_T1;
    const float* w = X ? g_w2 : g_w1;
    float* Gm = X ? g_Gm2 : g_Gm1;
    float* u  = X ? g_u2  : g_u1;
    float* v  = X ? g_v2  : g_v1;
    if (b < 32) {
        float a = 0.f;
        #pragma unroll 8
        for (int k=0;k<128;k++) a += T[b*128+k]*Wu[k*128+c];
        Gm[b*128+c] = a;
    } else if (b == 32) {
        float a = 0.f;
        #pragma unroll 8
        for (int k=0;k<128;k++) a += w[k]*Wu[k*128+c];
        u[c] = a;
    } else {
        float a = bu[c];
        #pragma unroll 8
        for (int k=0;k<128;k++) a += (bn[k]+be[k])*Wu[k*128+c];
        v[c] = a;
    }
}

// D_X[i,:] = S[i,:] @ G_X + deg[i]*u_X + v_X
__global__ void D_kernel() {
    __shared__ float G1s[EIN*HH];
    __shared__ float G2s[EIN*HH];
    __shared__ float Ssh[EIN];
    int c = threadIdx.x;
    for (int k=c; k<EIN*HH; k+=128) { G1s[k]=g_Gm1[k]; G2s[k]=g_Gm2[k]; }
    float u1=g_u1[c], u2=g_u2[c], v1=g_v1[c], v2=g_v2[c];
    __syncthreads();
    for (int i=blockIdx.x; i<NN; i+=gridDim.x) {
        if (c<EIN) Ssh[c] = g_S[i*EIN+c];
        __syncthreads();
        float dg = (float)g_deg[i];
        float a1 = v1 + dg*u1, a2 = v2 + dg*u2;
        #pragma unroll
        for (int k=0;k<EIN;k++){ float s=Ssh[k]; a1 += s*G1s[k*HH+c]; a2 += s*G2s[k*HH+c]; }
        g_D1[i*HH+c] = a1;
        g_D2[i*HH+c] = a2;
        __syncthreads();
    }
}

// ---------------- warp-specialized persistent fused conv ----------------
// producers (warps 0-7): G[tile] = (A+I) h  (32 rows, double buffered)
// consumers (warps 8-15): hout = relu(G @ M + D)   (or x-proj: G @ M + bias, no relu)
#define CSMEM ((HH*HH + 2*TR*HH)*4)   // 64KB M + 2x16KB G = 96KB

#define BARSYNC(id) asm volatile("bar.sync %0, 512;" :: "r"(id) : "memory")
#define BARARR(id)  asm volatile("bar.arrive %0, 512;" :: "r"(id) : "memory")

template<bool PROJ>
__global__ void __launch_bounds__(512, 1)
conv_ws(const float* __restrict__ xin, const float* __restrict__ Mext,
        const float* __restrict__ bias, int which, int dstA)
{
    extern __shared__ float smem[];
    float* Ms  = smem;                 // [128][128]
    float* Gs0 = smem + HH*HH;         // [32][128]
    float* Gs1 = Gs0 + TR*HH;

    const float* M   = PROJ ? Mext : (which ? g_M2 : g_M1);
    const float* hin = PROJ ? xin  : (dstA ? g_hB : g_hA);
    const float* D   = PROJ ? (const float*)nullptr : (which ? g_D2 : g_D1);
    float* hout = dstA ? g_hA : g_hB;

    int tid = threadIdx.x;
    for (int i = tid; i < HH*HH/4; i += 512)
        ((float4*)Ms)[i] = ((const float4*)M)[i];
    __syncthreads();

    int wid = tid >> 5, lane = tid & 31;

    if (wid < 8) {
        // ---------------- producer ----------------
        int idx = 0;
        for (int tile = blockIdx.x; tile < NT2; tile += gridDim.x, idx++) {
            int bufb = idx & 1;
            if (idx >= 2) BARSYNC(3 + bufb);
            float* G = bufb ? Gs1 : Gs0;
            int row0 = tile * TR;
            for (int n = wid; n < TR; n += 8) {
                int i = row0 + n;
                float4 z = make_float4(0.f,0.f,0.f,0.f);
                float4 a0=z,a1=z,a2=z,a3=z,a4=z,a5=z,a6=z,a7=z;
                if (i < NN) {
                    const float* hl = hin + lane*4;
                    a0 = *(const float4*)(hl + i*HH);
                    if (!PROJ) {
                        int s = g_rowptr[i], e = g_rowptr[i+1];
                        if (s < e) {
                            int nIt = (e - s) >> 3;
                            const int4* cp = (const int4*)(g_csr + s);  // 4 int4 = 8 int2 per iter
                            int4 c0 = cp[0], c1 = cp[1], c2 = cp[2], c3 = cp[3];
                            for (int it = 0; it < nIt; it++) {
                                // prefetch next iteration's indices (clamped)
                                int nx = (it + 1 < nIt) ? (it + 1) : it;
                                const int4* cq = cp + nx*4;
                                int4 d0 = cq[0], d1 = cq[1], d2 = cq[2], d3 = cq[3];
                                float4 b0 = *(const float4*)(hl + c0.x*HH);
                                float4 b1 = *(const float4*)(hl + c0.z*HH);
                                float4 b2 = *(const float4*)(hl + c1.x*HH);
                                float4 b3 = *(const float4*)(hl + c1.z*HH);
                                float4 b4 = *(const float4*)(hl + c2.x*HH);
                                float4 b5 = *(const float4*)(hl + c2.z*HH);
                                float4 b6 = *(const float4*)(hl + c3.x*HH);
                                float4 b7 = *(const float4*)(hl + c3.z*HH);
                                F4ACC(a0,b0); F4ACC(a1,b1); F4ACC(a2,b2); F4ACC(a3,b3);
                                F4ACC(a4,b4); F4ACC(a5,b5); F4ACC(a6,b6); F4ACC(a7,b7);
                                c0 = d0; c1 = d1; c2 = d2; c3 = d3;
                            }
                        }
                    }
                }
                F4ACC(a0,a1); F4ACC(a2,a3); F4ACC(a4,a5); F4ACC(a6,a7);
                F4ACC(a0,a2); F4ACC(a4,a6); F4ACC(a0,a4);
                *(float4*)(G + n*HH + lane*4) = a0;
            }
            BARARR(1 + bufb);
        }
    } else {
        // ---------------- consumer ----------------
        int ct = tid - 256;            // 0..255
        int tx = ct & 31;              // col group (4 cols)
        int ty = ct >> 5;              // 0..7 row group (4 rows)
        int colb = tx * 4;
        int idx = 0;
        for (int tile = blockIdx.x; tile < NT2; tile += gridDim.x, idx++) {
            int bufb = idx & 1;
            int row0 = tile * TR;
            float4 acc[4];
            if (PROJ) {
                float4 cb = *(const float4*)(bias + colb);
                #pragma unroll
                for (int r=0;r<4;r++) acc[r] = cb;
            } else {
                #pragma unroll
                for (int r=0;r<4;r++) {
                    int gi = row0 + ty*4 + r;
                    acc[r] = (gi < NN) ? *(const float4*)(D + gi*HH + colb)
                                       : make_float4(0.f,0.f,0.f,0.f);
                }
            }
            BARSYNC(1 + bufb);
            const float* G = (bufb ? Gs1 : Gs0) + ty*4*HH;
            #pragma unroll 4
            for (int k0 = 0; k0 < HH; k0 += 4) {
                float4 g0 = *(const float4*)(G + 0*HH + k0);
                float4 g1 = *(const float4*)(G + 1*HH + k0);
                float4 g2 = *(const float4*)(G + 2*HH + k0);
                float4 g3 = *(const float4*)(G + 3*HH + k0);
                float4 m0 = *(const float4*)(Ms + (k0+0)*HH + colb);
                float4 m1 = *(const float4*)(Ms + (k0+1)*HH + colb);
                float4 m2 = *(const float4*)(Ms + (k0+2)*HH + colb);
                float4 m3 = *(const float4*)(Ms + (k0+3)*HH + colb);
                F4FMA(acc[0], g0.x, m0); F4FMA(acc[0], g0.y, m1);
                F4FMA(acc[0], g0.z, m2); F4FMA(acc[0], g0.w, m3);
                F4FMA(acc[1], g1.x, m0); F4FMA(acc[1], g1.y, m1);
                F4FMA(acc[1], g1.z, m2); F4FMA(acc[1], g1.w, m3);
                F4FMA(acc[2], g2.x, m0); F4FMA(acc[2], g2.y, m1);
                F4FMA(acc[2], g2.z, m2); F4FMA(acc[2], g2.w, m3);
                F4FMA(acc[3], g3.x, m0); F4FMA(acc[3], g3.y, m1);
                F4FMA(acc[3], g3.z, m2); F4FMA(acc[3], g3.w, m3);
            }
            BARARR(3 + bufb);
            #pragma unroll
            for (int r=0;r<4;r++) {
                int gi = row0 + ty*4 + r;
                if (gi < NN) {
                    float4 o = acc[r];
                    if (!PROJ) {
                        o.x=fmaxf(o.x,0.f); o.y=fmaxf(o.y,0.f);
                        o.z=fmaxf(o.z,0.f); o.w=fmaxf(o.w,0.f);
                    }
                    *(float4*)(hout + gi*HH + colb) = o;
                }
            }
        }
    }
}

// ---------------- pooling (batch sorted -> run-based partial reduce) ----------------
__global__ void pool_kernel(const int* __restrict__ batch) {
    __shared__ int bsh[128];
    int c = threadIdx.x;
    int s = blockIdx.x*128;
    int nloc = NN - s; if (nloc > 128) nloc = 128;
    for (int i=c; i<nloc; i+=128) bsh[i] = batch[s+i];
    __syncthreads();
    const float* h = g_hA;
    float sum=0.f, mx=0.f; int cnt=0;
    int cur = bsh[0];
    for (int i=0;i<nloc;i++) {
        int g = bsh[i];
        if (g != cur) {
            atomicAdd(&g_psum[cur*HH+c], sum);
            atomicMax((unsigned int*)&g_pmax[cur*HH+c], __float_as_uint(mx));
            if (c==0) atomicAdd(&g_cnt[cur], cnt);
            cur=g; sum=0.f; mx=0.f; cnt=0;
        }
        float v = h[(s+i)*HH + c];
        sum += v; mx = fmaxf(mx, v); cnt++;
    }
    atomicAdd(&g_psum[cur*HH+c], sum);
    atomicMax((unsigned int*)&g_pmax[cur*HH+c], __float_as_uint(mx));
    if (c==0) atomicAdd(&g_cnt[cur], cnt);
}

// ---------------- readout head ----------------
__global__ void head_kernel(const float* __restrict__ Wm1, const float* __restrict__ bm1,
                            const float* __restrict__ Wm2, const float* __restrict__ bm2,
                            float* __restrict__ out) {
    __shared__ float pooled[2*HH];
    __shared__ float z1[HH];
    int g = blockIdx.x, c = threadIdx.x;
    float denom = fmaxf((float)g_cnt[g], 1.f);
    pooled[c]    = g_psum[g*HH+c] / denom;
    pooled[HH+c] = g_pmax[g*HH+c];
    __syncthreads();
    float a = bm1[c];
    #pragma unroll 8
    for (int k=0;k<2*HH;k++) a += pooled[k]*Wm1[k*HH+c];
    z1[c] = fmaxf(a, 0.f);
    __syncthreads();
    if (c < 2) {
        float o = bm2[c];
        for (int k=0;k<HH;k++) o += z1[k]*Wm2[k*2+c];
        out[g*2+c] = 1.f/(1.f+expf(-o));
    }
}

// ---------------- launch ----------------
extern "C" void kernel_launch(void* const* d_in, const int* in_sizes, int n_in,
                              void* d_out, int out_size) {
    const float* x         = (const float*)d_in[0];
    const float* edge_attr = (const float*)d_in[1];
    const int*   ei        = (const int*)  d_in[2];
    const int*   batch     = (const int*)  d_in[3];
    const float* Wn2l = (const float*)d_in[4];
    const float* bn2l = (const float*)d_in[5];
    const float* We2l = (const float*)d_in[6];
    const float* be2l = (const float*)d_in[7];
    const float* Wn1  = (const float*)d_in[8];
    const float* bn1  = (const float*)d_in[9];
    const float* We1  = (const float*)d_in[10];
    const float* be1  = (const float*)d_in[11];
    const float* Wu1  = (const float*)d_in[12];
    const float* bu1  = (const float*)d_in[13];
    const float* Wn2  = (const float*)d_in[14];
    const float* bn2  = (const float*)d_in[15];
    const float* We2  = (const float*)d_in[16];
    const float* be2  = (const float*)d_in[17];
    const float* Wu2  = (const float*)d_in[18];
    const float* bu2  = (const float*)d_in[19];
    const float* Wm1  = (const float*)d_in[20];
    const float* bm1  = (const float*)d_in[21];
    const float* Wm2  = (const float*)d_in[22];
    const float* bm2  = (const float*)d_in[23];
    float* out = (float*)d_out;

    const int* src = ei;
    const int* dst = ei + EE;

    cudaFuncSetAttribute(conv_ws<true>,  cudaFuncAttributeMaxDynamicSharedMemorySize, CSMEM);
    cudaFuncSetAttribute(conv_ws<false>, cudaFuncAttributeMaxDynamicSharedMemorySize, CSMEM);

    init_zero<<<160, 256>>>();
    deg_kernel<<<(EE+255)/256, 256>>>(dst);
    scan1_kernel<<<NSB, 256>>>();
    // projection (independent of CSR) — placed early
    conv_ws<true><<<NBLK, 512, CSMEM>>>(x, Wn2l, bn2l, 0, /*dstA=*/1);
    scan2_kernel<<<1, 128>>>();
    scan3_kernel<<<NSB, 256>>>();
    fill_kernel<<<(EE+255)/256, 256>>>(src, dst);
    pad_kernel<<<(NN+255)/256, 256>>>();
    S_kernel<<<(NN*32)/256, 256>>>(edge_attr);

    tinyA<<<161, 128>>>(Wn1, Wu1, We1, We2l, be2l, be1, bn1, 0);
    tinyA<<<161, 128>>>(Wn2, Wu2, We2, We2l, be2l, be2, bn2, 1);
    tinyB<<<34, 128>>>(Wu1, bn1, be1, bu1, 0);
    tinyB<<<34, 128>>>(Wu2, bn2, be2, bu2, 1);
    D_kernel<<<296, 128>>>();

    // 3 x (conv1, conv2): ping-pong hA <-> hB, final result in hA
    conv_ws<false><<<NBLK, 512, CSMEM>>>(nullptr, nullptr, nullptr, 0, 0); // A->B
    conv_ws<false><<<NBLK, 512, CSMEM>>>(nullptr, nullptr, nullptr, 1, 1); // B->A
    conv_ws<false><<<NBLK, 512, CSMEM>>>(nullptr, nullptr, nullptr, 0, 0);
    conv_ws<false><<<NBLK, 512, CSMEM>>>(nullptr, nullptr, nullptr, 1, 1);
    conv_ws<false><<<NBLK, 512, CSMEM>>>(nullptr, nullptr, nullptr, 0, 0);
    conv_ws<false><<<NBLK, 512, CSMEM>>>(nullptr, nullptr, nullptr, 1, 1);

    pool_kernel<<<(NN+127)/128, 128>>>(batch);
    head_kernel<<<GGR, 128>>>(Wm1, bm1, Wm2, bm2, out);
}